// round 12
// baseline (speedup 1.0000x reference)
#include <cuda_runtime.h>
#include <cuda_bf16.h>
#include <cstdint>

#define THREADS 512
#define VT      128000
#define VS      32000
#define KSEL    256
#define MAXB    2048
#define NSTAGE     4
#define TILE_F4    500            // 2000 floats = 8000 bytes per tile
#define TILE_BYTES 8000
#define NTILES     64             // 64 * 8000 B = 512000 B = one row

struct __align__(128) Smem {
    float4   buf[NSTAGE][TILE_F4];       // 32000 B; aliased as radix ping arrays later
    unsigned tKey0[MAXB], tIdx0[MAXB];   // 16384 B candidate store
    unsigned long long mbar[NSTAGE];
    unsigned selKey[KSEL], selIdx[KSEL];
    float    fred[THREADS], fred2[THREADS];
    int      s_bin; unsigned s_above;
    int      nCand, selCount, nNext, s_is64;
    unsigned s_maxkey, s_minkey;
    float    s_mean, s_std, s_denom;
};

// monotone float->uint key
__device__ __forceinline__ unsigned f2k(float x) {
    unsigned u = __float_as_uint(x);
    return (u & 0x80000000u) ? ~u : (u | 0x80000000u);
}
__device__ __forceinline__ float k2f(unsigned k) {
    unsigned u = (k & 0x80000000u) ? (k & 0x7fffffffu) : ~k;
    return __uint_as_float(u);
}
__device__ __forceinline__ unsigned s2u(const void* p) {
    unsigned a;
    asm("{ .reg .u64 t; cvta.to.shared.u64 t, %1; cvt.u32.u64 %0, t; }"
        : "=r"(a) : "l"(p));
    return a;
}
__device__ __forceinline__ void mbar_init(unsigned a, unsigned cnt) {
    asm volatile("mbarrier.init.shared.b64 [%0], %1;" :: "r"(a), "r"(cnt) : "memory");
}
__device__ __forceinline__ void mbar_expect(unsigned a, unsigned bytes) {
    asm volatile("mbarrier.arrive.expect_tx.shared.b64 _, [%0], %1;"
                 :: "r"(a), "r"(bytes) : "memory");
}
__device__ __forceinline__ void bulk_g2s(unsigned dst, const void* src,
                                         unsigned bytes, unsigned mbar) {
    asm volatile("cp.async.bulk.shared::cta.global.mbarrier::complete_tx::bytes "
                 "[%0], [%1], %2, [%3];"
                 :: "r"(dst), "l"(src), "r"(bytes), "r"(mbar) : "memory");
}
__device__ __forceinline__ void mbar_wait(unsigned a, unsigned parity) {
    unsigned done;
    asm volatile(
        "{\n\t.reg .pred p;\n\t"
        "mbarrier.try_wait.parity.acquire.cta.shared::cta.b64 p, [%1], %2;\n\t"
        "selp.b32 %0, 1, 0, p;\n\t}"
        : "=r"(done) : "r"(a), "r"(parity) : "memory");
    if (!done) {
        asm volatile(
            "{\n\t.reg .pred P1;\n\t"
            "WL%=:\n\t"
            "mbarrier.try_wait.parity.acquire.cta.shared::cta.b64 P1, [%0], %1, 0x989680;\n\t"
            "@P1 bra.uni WD%=;\n\t"
            "bra.uni WL%=;\n\t"
            "WD%=:\n\t}"
            :: "r"(a), "r"(parity) : "memory");
    }
}

extern __shared__ char smem_raw[];

__global__ void __launch_bounds__(THREADS)
vocab_project_kernel(const float* __restrict__ logits,
                     const void* __restrict__ mapping,
                     float* __restrict__ out) {
    Smem* sm = (Smem*)smem_raw;
    const int tid = threadIdx.x;
    const int row = blockIdx.x;
    const float* __restrict__ rowf = logits + (size_t)row * VT;
    const char*  rowb = (const char*)rowf;
    float* __restrict__ orow = out + (size_t)row * VS;

    unsigned mb[NSTAGE], bu[NSTAGE];
#pragma unroll
    for (int s = 0; s < NSTAGE; s++) {
        mb[s] = s2u(&sm->mbar[s]);
        bu[s] = s2u(&sm->buf[s][0]);
    }

    if (tid == 0) {
        const unsigned* m32 = (const unsigned*)mapping;
        int all0 = 1;
        for (int i = 1; i < 64; i += 2)
            if (m32[i] != 0u) { all0 = 0; break; }
        sm->s_is64 = all0;
        sm->s_denom = 0.0f;
        sm->selCount = 0;
#pragma unroll
        for (int s = 0; s < NSTAGE; s++) mbar_init(mb[s], 1);
    }
    __syncthreads();

    // ---- streamed collection: 4-deep bulk-async pipeline ----
    unsigned phmask = 0;            // per-stage parity bits (persist across retries)
    float thrVal = 2.45f;           // E[count] ~ 915 for N(0,1)
    float stdGuess = 1.0f;
    bool haveStats = false;
    for (int attempt = 0; attempt < 10; attempt++) {
        if (tid == 0) { sm->nCand = 0; sm->s_maxkey = 0u; sm->s_minkey = 0xFFFFFFFFu; }
        __syncthreads();
        if (tid == 0) {
#pragma unroll
            for (int s = 0; s < 3; s++) {       // prefetch 3 tiles
                mbar_expect(mb[s], TILE_BYTES);
                bulk_g2s(bu[s], rowb + (size_t)s * TILE_BYTES, TILE_BYTES, mb[s]);
            }
        }
        for (int k = 0; k < NTILES; k++) {
            const int st = k & (NSTAGE - 1);
            mbar_wait(mb[st], (phmask >> st) & 1u);
            phmask ^= 1u << st;
            // prefetch tile k+3 into its stage (freed at sync of iter k-1)
            const int nk = k + 3;
            if (nk < NTILES && tid == 0) {
                const int ns = nk & (NSTAGE - 1);
                mbar_expect(mb[ns], TILE_BYTES);
                bulk_g2s(bu[ns], rowb + (size_t)nk * TILE_BYTES, TILE_BYTES, mb[ns]);
            }
            const float4* tb = sm->buf[st];
            const unsigned base = (unsigned)k * (TILE_F4 * 4);
            if (tid < TILE_F4) {
                float4 v = tb[tid];
                float m = fmaxf(fmaxf(v.x, v.y), fmaxf(v.z, v.w));
                if (m >= thrVal) {
                    float a4[4] = {v.x, v.y, v.z, v.w};
#pragma unroll
                    for (int j = 0; j < 4; j++) {
                        if (a4[j] >= thrVal) {
                            unsigned key = f2k(a4[j]);
                            int p = atomicAdd(&sm->nCand, 1);
                            if (p < MAXB) {
                                sm->tKey0[p] = key;
                                sm->tIdx0[p] = base + tid * 4 + j;
                                atomicMax(&sm->s_maxkey, key);
                                atomicMin(&sm->s_minkey, key);
                            }
                        }
                    }
                }
            }
            __syncthreads();            // all threads done with buf[st]
        }
        __syncthreads();
        int nc = sm->nCand;
        if (nc >= KSEL && nc <= MAXB) break;
        // rare fallback: sampled stats, adjust threshold, re-stream
        if (!haveStats) {
            float x = rowf[tid * (VT / THREADS)];
            sm->fred[tid] = x;
            sm->fred2[tid] = x * x;
            __syncthreads();
            for (int s = THREADS / 2; s > 0; s >>= 1) {
                if (tid < s) {
                    sm->fred[tid] += sm->fred[tid + s];
                    sm->fred2[tid] += sm->fred2[tid + s];
                }
                __syncthreads();
            }
            if (tid == 0) {
                float mean = sm->fred[0] * (1.0f / THREADS);
                float var  = sm->fred2[0] * (1.0f / THREADS) - mean * mean;
                sm->s_mean = mean;
                sm->s_std  = sqrtf(fmaxf(var, 1e-12f));
            }
            __syncthreads();
            stdGuess = sm->s_std;
            float cand = sm->s_mean + 2.45f * sm->s_std;
            if (fabsf(cand - thrVal) < 0.05f * sm->s_std)
                cand += (nc < KSEL) ? -0.60f * sm->s_std : 0.35f * sm->s_std;
            thrVal = cand;
            haveStats = true;
        } else {
            if (nc < KSEL) thrVal -= 0.60f * stdGuess + 1e-6f;
            else           thrVal += 0.35f * stdGuess + 1e-6f;
        }
        __syncthreads();
    }

    // ---- zero own output row ----
    {
        float4 z = make_float4(0.f, 0.f, 0.f, 0.f);
        float4* op = (float4*)orow;
        for (int i = tid; i < VS / 4; i += THREADS) op[i] = z;
    }

    // ---- exact top-KSEL: byte-radix select from highest differing byte ----
    // ping arrays aliased onto the (now idle) stream buffers
    unsigned* keyArr[2] = { sm->tKey0, (unsigned*)&sm->buf[0][0] };
    unsigned* idxArr[2] = { sm->tIdx0, (unsigned*)&sm->buf[0][0] + MAXB };
    unsigned* hist = (unsigned*)sm->fred;   // 256 x 4B histogram

    int cur = 0;
    int curN = sm->nCand < MAXB ? sm->nCand : MAXB;
    int need = KSEL;
    const unsigned keyxor = sm->s_minkey ^ sm->s_maxkey;
    int level_start = (keyxor == 0u) ? -1 : (3 - (__clz(keyxor) >> 3));
    __syncthreads();

    for (int level = level_start; level >= 0 && need > 0; level--) {
        if (curN == need) {
            for (int p = tid; p < curN; p += THREADS) {
                int q = atomicAdd(&sm->selCount, 1);
                sm->selKey[q] = keyArr[cur][p];
                sm->selIdx[q] = idxArr[cur][p];
            }
            need = 0;
            __syncthreads();
            break;
        }
        if (tid < 256) hist[tid] = 0u;
        __syncthreads();
        const int sh = level * 8;
        for (int p = tid; p < curN; p += THREADS)
            atomicAdd(&hist[(keyArr[cur][p] >> sh) & 0xFFu], 1u);
        __syncthreads();
        if (tid < 32) {
            unsigned local[8];
            unsigned part = 0;
#pragma unroll
            for (int j = 0; j < 8; j++) {
                local[j] = hist[255 - (tid * 8 + j)];
                part += local[j];
            }
            unsigned incl = part;
#pragma unroll
            for (int off = 1; off < 32; off <<= 1) {
                unsigned v = __shfl_up_sync(0xffffffffu, incl, off);
                if (tid >= off) incl += v;
            }
            unsigned before = incl - part;
            if (before < (unsigned)need && incl >= (unsigned)need) {
                unsigned cum = before;
#pragma unroll
                for (int j = 0; j < 8; j++) {
                    unsigned cj = local[j];
                    if (cum + cj >= (unsigned)need) {
                        sm->s_bin = 255 - (tid * 8 + j);
                        sm->s_above = cum;
                        break;
                    }
                    cum += cj;
                }
            }
        }
        if (tid == 0) sm->nNext = 0;
        __syncthreads();
        const int c = sm->s_bin;
        const int G = (int)sm->s_above;
        const int oth = cur ^ 1;
        for (int p = tid; p < curN; p += THREADS) {
            unsigned key = keyArr[cur][p];
            int byte = (int)((key >> sh) & 0xFFu);
            if (byte > c) {
                int q = atomicAdd(&sm->selCount, 1);
                sm->selKey[q] = key; sm->selIdx[q] = idxArr[cur][p];
            } else if (byte == c) {
                int q = atomicAdd(&sm->nNext, 1);
                keyArr[oth][q] = key; idxArr[oth][q] = idxArr[cur][p];
            }
        }
        __syncthreads();
        need -= G;
        curN = sm->nNext;
        cur = oth;
        __syncthreads();
    }

    // identical keys remain; take `need` smallest indices
    if (need > 0) {
        for (int p = tid; p < curN; p += THREADS) {
            unsigned my = idxArr[cur][p];
            int rank = 0;
            for (int j = 0; j < curN; j++) rank += (idxArr[cur][j] < my);
            if (rank < need) {
                int q = atomicAdd(&sm->selCount, 1);
                sm->selKey[q] = keyArr[cur][p];
                sm->selIdx[q] = my;
            }
        }
        __syncthreads();
    }

    const float vmax = k2f(sm->s_maxkey);

    // ---- weights + denominator ----
    float w = 0.0f;
    if (tid < KSEL) {
        w = exp2f((k2f(sm->selKey[tid]) - vmax) * 0.36067376022224085f); // 1/(4 ln2)
        float ws = w;
#pragma unroll
        for (int off = 16; off > 0; off >>= 1)
            ws += __shfl_xor_sync(0xffffffffu, ws, off);
        if ((tid & 31) == 0) atomicAdd(&sm->s_denom, ws);
    }
    __syncthreads();
    const float inv = 1.0f / sm->s_denom;

    // ---- scatter ----
    if (tid < KSEL) {
        unsigned idx = sm->selIdx[tid];
        int sid;
        if (sm->s_is64) sid = (int)((const long long*)mapping)[idx];
        else            sid = ((const int*)mapping)[idx];
        atomicAdd(&orow[sid], w * inv);
    }
}

extern "C" void kernel_launch(void* const* d_in, const int* in_sizes, int n_in,
                              void* d_out, int out_size) {
    const float* logits  = (const float*)d_in[0];
    const void*  mapping = d_in[1];
    float* out = (float*)d_out;
    int rows = in_sizes[0] / VT;   // B*T = 2048
    int shbytes = (int)sizeof(Smem);
    cudaFuncSetAttribute(vocab_project_kernel,
                         cudaFuncAttributeMaxDynamicSharedMemorySize, shbytes);
    vocab_project_kernel<<<rows, THREADS, shbytes>>>(logits, mapping, out);
}

// round 13
// speedup vs baseline: 1.1956x; 1.1956x over previous
#include <cuda_runtime.h>
#include <cuda_bf16.h>
#include <cstdint>

#define THREADS 512
#define VT      128000
#define VS      32000
#define KSEL    256
#define MAXB    2048
#define TILE_F4    1000          // 4000 floats = 16000 bytes per tile
#define TILE_BYTES 16000
#define NTILES     32            // 32 * 16000 B = one 512000 B row

struct __align__(128) Smem {
    float4   buf[2][TILE_F4];            // 32000 B; aliased as radix ping arrays later
    unsigned tKey0[MAXB], tIdx0[MAXB];   // 16384 B candidate store
    unsigned long long mbar[2];
    unsigned selKey[KSEL], selIdx[KSEL];
    float    fred[THREADS], fred2[THREADS];
    int      s_bin; unsigned s_above;
    int      nCand, selCount, nNext, s_is64;
    unsigned s_maxkey, s_minkey;
    float    s_mean, s_std, s_denom;
};

// monotone float->uint key
__device__ __forceinline__ unsigned f2k(float x) {
    unsigned u = __float_as_uint(x);
    return (u & 0x80000000u) ? ~u : (u | 0x80000000u);
}
__device__ __forceinline__ float k2f(unsigned k) {
    unsigned u = (k & 0x80000000u) ? (k & 0x7fffffffu) : ~k;
    return __uint_as_float(u);
}
__device__ __forceinline__ unsigned s2u(const void* p) {
    unsigned a;
    asm("{ .reg .u64 t; cvta.to.shared.u64 t, %1; cvt.u32.u64 %0, t; }"
        : "=r"(a) : "l"(p));
    return a;
}
__device__ __forceinline__ void mbar_init(unsigned a, unsigned cnt) {
    asm volatile("mbarrier.init.shared.b64 [%0], %1;" :: "r"(a), "r"(cnt) : "memory");
}
__device__ __forceinline__ void mbar_expect(unsigned a, unsigned bytes) {
    asm volatile("mbarrier.arrive.expect_tx.shared.b64 _, [%0], %1;"
                 :: "r"(a), "r"(bytes) : "memory");
}
__device__ __forceinline__ void bulk_g2s(unsigned dst, const void* src,
                                         unsigned bytes, unsigned mbar) {
    asm volatile("cp.async.bulk.shared::cta.global.mbarrier::complete_tx::bytes "
                 "[%0], [%1], %2, [%3];"
                 :: "r"(dst), "l"(src), "r"(bytes), "r"(mbar) : "memory");
}
__device__ __forceinline__ void mbar_wait(unsigned a, unsigned parity) {
    unsigned done;
    asm volatile(
        "{\n\t.reg .pred p;\n\t"
        "mbarrier.try_wait.parity.acquire.cta.shared::cta.b64 p, [%1], %2;\n\t"
        "selp.b32 %0, 1, 0, p;\n\t}"
        : "=r"(done) : "r"(a), "r"(parity) : "memory");
    if (!done) {
        asm volatile(
            "{\n\t.reg .pred P1;\n\t"
            "WL%=:\n\t"
            "mbarrier.try_wait.parity.acquire.cta.shared::cta.b64 P1, [%0], %1, 0x989680;\n\t"
            "@P1 bra.uni WD%=;\n\t"
            "bra.uni WL%=;\n\t"
            "WD%=:\n\t}"
            :: "r"(a), "r"(parity) : "memory");
    }
}

extern __shared__ char smem_raw[];

__global__ void __launch_bounds__(THREADS)
vocab_project_kernel(const float* __restrict__ logits,
                     const void* __restrict__ mapping,
                     float* __restrict__ out) {
    Smem* sm = (Smem*)smem_raw;
    const int tid = threadIdx.x;
    const int row = blockIdx.x;
    const float* __restrict__ rowf = logits + (size_t)row * VT;
    const char*  rowb = (const char*)rowf;
    float* __restrict__ orow = out + (size_t)row * VS;

    const unsigned mb0 = s2u(&sm->mbar[0]);
    const unsigned mb1 = s2u(&sm->mbar[1]);
    const unsigned bu0 = s2u(&sm->buf[0][0]);
    const unsigned bu1 = s2u(&sm->buf[1][0]);

    if (tid == 0) {
        const unsigned* m32 = (const unsigned*)mapping;
        int all0 = 1;
        for (int i = 1; i < 64; i += 2)
            if (m32[i] != 0u) { all0 = 0; break; }
        sm->s_is64 = all0;
        sm->s_denom = 0.0f;
        sm->selCount = 0;
        mbar_init(mb0, 1);
        mbar_init(mb1, 1);
    }
    __syncthreads();

    // ---- streamed collection via bulk-async double buffer ----
    int ph0 = 0, ph1 = 0;           // per-buffer mbarrier phase (persists across retries)
    float thrVal = 2.45f;           // E[count] ~ 915 for N(0,1)
    float stdGuess = 1.0f;
    bool haveStats = false;
    for (int attempt = 0; attempt < 10; attempt++) {
        if (tid == 0) { sm->nCand = 0; sm->s_maxkey = 0u; sm->s_minkey = 0xFFFFFFFFu; }
        __syncthreads();
        if (tid == 0) {
            mbar_expect(mb0, TILE_BYTES);
            bulk_g2s(bu0, rowb + 0 * TILE_BYTES, TILE_BYTES, mb0);
            mbar_expect(mb1, TILE_BYTES);
            bulk_g2s(bu1, rowb + 1 * TILE_BYTES, TILE_BYTES, mb1);
        }
        for (int k = 0; k < NTILES; k++) {
            const int b = k & 1;
            if (b == 0) { mbar_wait(mb0, ph0); ph0 ^= 1; }
            else        { mbar_wait(mb1, ph1); ph1 ^= 1; }
            const float4* tb = sm->buf[b];
            const unsigned base = (unsigned)k * (TILE_F4 * 4);
            for (int i = tid; i < TILE_F4; i += THREADS) {
                float4 v = tb[i];
                float m = fmaxf(fmaxf(v.x, v.y), fmaxf(v.z, v.w));
                if (m >= thrVal) {
                    float a4[4] = {v.x, v.y, v.z, v.w};
#pragma unroll
                    for (int j = 0; j < 4; j++) {
                        if (a4[j] >= thrVal) {
                            unsigned key = f2k(a4[j]);
                            int p = atomicAdd(&sm->nCand, 1);
                            if (p < MAXB) {
                                sm->tKey0[p] = key;
                                sm->tIdx0[p] = base + i * 4 + j;
                                atomicMax(&sm->s_maxkey, key);
                                atomicMin(&sm->s_minkey, key);
                            }
                        }
                    }
                }
            }
            __syncthreads();            // everyone done reading buf b
            const int nk = k + 2;
            if (nk < NTILES && tid == 0) {
                const unsigned mb = b ? mb1 : mb0;
                const unsigned bu = b ? bu1 : bu0;
                mbar_expect(mb, TILE_BYTES);
                bulk_g2s(bu, rowb + (size_t)nk * TILE_BYTES, TILE_BYTES, mb);
            }
        }
        __syncthreads();
        int nc = sm->nCand;
        if (nc >= KSEL && nc <= MAXB) break;
        // rare fallback: sampled stats, adjust threshold, re-stream
        if (!haveStats) {
            float x = rowf[tid * (VT / THREADS)];
            sm->fred[tid] = x;
            sm->fred2[tid] = x * x;
            __syncthreads();
            for (int s = THREADS / 2; s > 0; s >>= 1) {
                if (tid < s) {
                    sm->fred[tid] += sm->fred[tid + s];
                    sm->fred2[tid] += sm->fred2[tid + s];
                }
                __syncthreads();
            }
            if (tid == 0) {
                float mean = sm->fred[0] * (1.0f / THREADS);
                float var  = sm->fred2[0] * (1.0f / THREADS) - mean * mean;
                sm->s_mean = mean;
                sm->s_std  = sqrtf(fmaxf(var, 1e-12f));
            }
            __syncthreads();
            stdGuess = sm->s_std;
            float cand = sm->s_mean + 2.45f * sm->s_std;
            if (fabsf(cand - thrVal) < 0.05f * sm->s_std)
                cand += (nc < KSEL) ? -0.60f * sm->s_std : 0.35f * sm->s_std;
            thrVal = cand;
            haveStats = true;
        } else {
            if (nc < KSEL) thrVal -= 0.60f * stdGuess + 1e-6f;
            else           thrVal += 0.35f * stdGuess + 1e-6f;
        }
        __syncthreads();
    }

    // ---- zero own output row ----
    {
        float4 z = make_float4(0.f, 0.f, 0.f, 0.f);
        float4* op = (float4*)orow;
        for (int i = tid; i < VS / 4; i += THREADS) op[i] = z;
    }

    // ---- exact top-KSEL: byte-radix select from highest differing byte ----
    // ping arrays aliased onto the (now idle) stream buffers
    unsigned* keyArr[2] = { sm->tKey0, (unsigned*)&sm->buf[0][0] };
    unsigned* idxArr[2] = { sm->tIdx0, (unsigned*)&sm->buf[0][0] + MAXB };
    unsigned* hist = (unsigned*)sm->fred;   // 256 x 4B histogram

    int cur = 0;
    int curN = sm->nCand < MAXB ? sm->nCand : MAXB;
    int need = KSEL;
    const unsigned keyxor = sm->s_minkey ^ sm->s_maxkey;
    int level_start = (keyxor == 0u) ? -1 : (3 - (__clz(keyxor) >> 3));
    __syncthreads();

    for (int level = level_start; level >= 0 && need > 0; level--) {
        if (curN == need) {
            for (int p = tid; p < curN; p += THREADS) {
                int q = atomicAdd(&sm->selCount, 1);
                sm->selKey[q] = keyArr[cur][p];
                sm->selIdx[q] = idxArr[cur][p];
            }
            need = 0;
            __syncthreads();
            break;
        }
        if (tid < 256) hist[tid] = 0u;
        __syncthreads();
        const int sh = level * 8;
        for (int p = tid; p < curN; p += THREADS)
            atomicAdd(&hist[(keyArr[cur][p] >> sh) & 0xFFu], 1u);
        __syncthreads();
        if (tid < 32) {
            unsigned local[8];
            unsigned part = 0;
#pragma unroll
            for (int j = 0; j < 8; j++) {
                local[j] = hist[255 - (tid * 8 + j)];
                part += local[j];
            }
            unsigned incl = part;
#pragma unroll
            for (int off = 1; off < 32; off <<= 1) {
                unsigned v = __shfl_up_sync(0xffffffffu, incl, off);
                if (tid >= off) incl += v;
            }
            unsigned before = incl - part;
            if (before < (unsigned)need && incl >= (unsigned)need) {
                unsigned cum = before;
#pragma unroll
                for (int j = 0; j < 8; j++) {
                    unsigned cj = local[j];
                    if (cum + cj >= (unsigned)need) {
                        sm->s_bin = 255 - (tid * 8 + j);
                        sm->s_above = cum;
                        break;
                    }
                    cum += cj;
                }
            }
        }
        if (tid == 0) sm->nNext = 0;
        __syncthreads();
        const int c = sm->s_bin;
        const int G = (int)sm->s_above;
        const int oth = cur ^ 1;
        for (int p = tid; p < curN; p += THREADS) {
            unsigned key = keyArr[cur][p];
            int byte = (int)((key >> sh) & 0xFFu);
            if (byte > c) {
                int q = atomicAdd(&sm->selCount, 1);
                sm->selKey[q] = key; sm->selIdx[q] = idxArr[cur][p];
            } else if (byte == c) {
                int q = atomicAdd(&sm->nNext, 1);
                keyArr[oth][q] = key; idxArr[oth][q] = idxArr[cur][p];
            }
        }
        __syncthreads();
        need -= G;
        curN = sm->nNext;
        cur = oth;
        __syncthreads();
    }

    // identical keys remain; take `need` smallest indices
    if (need > 0) {
        for (int p = tid; p < curN; p += THREADS) {
            unsigned my = idxArr[cur][p];
            int rank = 0;
            for (int j = 0; j < curN; j++) rank += (idxArr[cur][j] < my);
            if (rank < need) {
                int q = atomicAdd(&sm->selCount, 1);
                sm->selKey[q] = keyArr[cur][p];
                sm->selIdx[q] = my;
            }
        }
        __syncthreads();
    }

    const float vmax = k2f(sm->s_maxkey);

    // ---- weights + denominator ----
    float w = 0.0f;
    if (tid < KSEL) {
        w = exp2f((k2f(sm->selKey[tid]) - vmax) * 0.36067376022224085f); // 1/(4 ln2)
        float ws = w;
#pragma unroll
        for (int off = 16; off > 0; off >>= 1)
            ws += __shfl_xor_sync(0xffffffffu, ws, off);
        if ((tid & 31) == 0) atomicAdd(&sm->s_denom, ws);
    }
    __syncthreads();
    const float inv = 1.0f / sm->s_denom;

    // ---- scatter ----
    if (tid < KSEL) {
        unsigned idx = sm->selIdx[tid];
        int sid;
        if (sm->s_is64) sid = (int)((const long long*)mapping)[idx];
        else            sid = ((const int*)mapping)[idx];
        atomicAdd(&orow[sid], w * inv);
    }
}

extern "C" void kernel_launch(void* const* d_in, const int* in_sizes, int n_in,
                              void* d_out, int out_size) {
    const float* logits  = (const float*)d_in[0];
    const void*  mapping = d_in[1];
    float* out = (float*)d_out;
    int rows = in_sizes[0] / VT;   // B*T = 2048
    int shbytes = (int)sizeof(Smem);
    cudaFuncSetAttribute(vocab_project_kernel,
                         cudaFuncAttributeMaxDynamicSharedMemorySize, shbytes);
    vocab_project_kernel<<<rows, THREADS, shbytes>>>(logits, mapping, out);
}

// round 14
// speedup vs baseline: 1.2390x; 1.0363x over previous
#include <cuda_runtime.h>
#include <cuda_bf16.h>
#include <cstdint>

#define THREADS 512
#define VT      128000
#define VS      32000
#define KSEL    256
#define MAXB    2048
#define TILE_F4    1000          // 4000 floats = 16000 bytes per tile
#define TILE_BYTES 16000
#define NTILES     32
#define GRID       592

__device__ int g_ctr = 0;        // rows handed out = GRID + g_ctr
__device__ int g_done = 0;

struct __align__(128) Smem {
    float4   buf[2][TILE_F4];            // 32000 B stream double buffer
    unsigned tKey0[MAXB], tIdx0[MAXB];   // 16384 B candidate store (in-place radix)
    unsigned long long mbar[2];
    unsigned selKey[KSEL], selIdx[KSEL];
    float    fred[THREADS], fred2[THREADS];
    int      s_bin; unsigned s_above;
    int      nCand, selCount, nNext, s_is64, s_next;
    unsigned s_maxkey, s_minkey;
    float    s_mean, s_std, s_denom;
};

__device__ __forceinline__ unsigned f2k(float x) {
    unsigned u = __float_as_uint(x);
    return (u & 0x80000000u) ? ~u : (u | 0x80000000u);
}
__device__ __forceinline__ float k2f(unsigned k) {
    unsigned u = (k & 0x80000000u) ? (k & 0x7fffffffu) : ~k;
    return __uint_as_float(u);
}
__device__ __forceinline__ unsigned s2u(const void* p) {
    unsigned a;
    asm("{ .reg .u64 t; cvta.to.shared.u64 t, %1; cvt.u32.u64 %0, t; }"
        : "=r"(a) : "l"(p));
    return a;
}
__device__ __forceinline__ void mbar_init(unsigned a, unsigned cnt) {
    asm volatile("mbarrier.init.shared.b64 [%0], %1;" :: "r"(a), "r"(cnt) : "memory");
}
__device__ __forceinline__ void mbar_expect(unsigned a, unsigned bytes) {
    asm volatile("mbarrier.arrive.expect_tx.shared.b64 _, [%0], %1;"
                 :: "r"(a), "r"(bytes) : "memory");
}
__device__ __forceinline__ void bulk_g2s(unsigned dst, const void* src,
                                         unsigned bytes, unsigned mbar) {
    asm volatile("cp.async.bulk.shared::cta.global.mbarrier::complete_tx::bytes "
                 "[%0], [%1], %2, [%3];"
                 :: "r"(dst), "l"(src), "r"(bytes), "r"(mbar) : "memory");
}
__device__ __forceinline__ void mbar_wait(unsigned a, unsigned parity) {
    unsigned done;
    asm volatile(
        "{\n\t.reg .pred p;\n\t"
        "mbarrier.try_wait.parity.acquire.cta.shared::cta.b64 p, [%1], %2;\n\t"
        "selp.b32 %0, 1, 0, p;\n\t}"
        : "=r"(done) : "r"(a), "r"(parity) : "memory");
    if (!done) {
        asm volatile(
            "{\n\t.reg .pred P1;\n\t"
            "WL%=:\n\t"
            "mbarrier.try_wait.parity.acquire.cta.shared::cta.b64 P1, [%0], %1, 0x989680;\n\t"
            "@P1 bra.uni WD%=;\n\t"
            "bra.uni WL%=;\n\t"
            "WD%=:\n\t}"
            :: "r"(a), "r"(parity) : "memory");
    }
}

extern __shared__ char smem_raw[];

__global__ void __launch_bounds__(THREADS)
vocab_project_kernel(const float* __restrict__ logits,
                     const void* __restrict__ mapping,
                     float* __restrict__ out,
                     int nrows) {
    Smem* sm = (Smem*)smem_raw;
    const int tid = threadIdx.x;

    const unsigned mb0 = s2u(&sm->mbar[0]);
    const unsigned mb1 = s2u(&sm->mbar[1]);
    const unsigned bu0 = s2u(&sm->buf[0][0]);
    const unsigned bu1 = s2u(&sm->buf[1][0]);

    if (tid == 0) {
        const unsigned* m32 = (const unsigned*)mapping;
        int all0 = 1;
        for (int i = 1; i < 64; i += 2)
            if (m32[i] != 0u) { all0 = 0; break; }
        sm->s_is64 = all0;
        mbar_init(mb0, 1);
        mbar_init(mb1, 1);
    }
    __syncthreads();

    int row = blockIdx.x;                 // first row = blockIdx
    int ph0 = 0, ph1 = 0;                 // persistent mbarrier phases

    // prologue: prefetch tiles 0,1 of first row
    if (row < nrows && tid == 0) {
        const char* rb = (const char*)(logits + (size_t)row * VT);
        mbar_expect(mb0, TILE_BYTES);
        bulk_g2s(bu0, rb, TILE_BYTES, mb0);
        mbar_expect(mb1, TILE_BYTES);
        bulk_g2s(bu1, rb + TILE_BYTES, TILE_BYTES, mb1);
    }

    while (row < nrows) {
        const float* __restrict__ rowf = logits + (size_t)row * VT;
        const char*  rowb = (const char*)rowf;
        float* __restrict__ orow = out + (size_t)row * VS;

        if (tid == 0) {
            sm->nCand = 0; sm->selCount = 0; sm->s_denom = 0.0f;
            sm->s_maxkey = 0u; sm->s_minkey = 0xFFFFFFFFu;
        }
        __syncthreads();

        // ---- stream row through double buffer (tiles 0,1 already in flight) ----
        const float thr0 = 2.45f;         // E[count] ~ 915 for N(0,1)
        for (int k = 0; k < NTILES; k++) {
            const int b = k & 1;
            if (b == 0) { mbar_wait(mb0, ph0); ph0 ^= 1; }
            else        { mbar_wait(mb1, ph1); ph1 ^= 1; }
            const float4* tb = sm->buf[b];
            const unsigned base = (unsigned)k * (TILE_F4 * 4);
            for (int i = tid; i < TILE_F4; i += THREADS) {
                float4 v = tb[i];
                float m = fmaxf(fmaxf(v.x, v.y), fmaxf(v.z, v.w));
                if (m >= thr0) {
                    float a4[4] = {v.x, v.y, v.z, v.w};
#pragma unroll
                    for (int j = 0; j < 4; j++) {
                        if (a4[j] >= thr0) {
                            unsigned key = f2k(a4[j]);
                            int p = atomicAdd(&sm->nCand, 1);
                            if (p < MAXB) {
                                sm->tKey0[p] = key;
                                sm->tIdx0[p] = base + i * 4 + j;
                                atomicMax(&sm->s_maxkey, key);
                                atomicMin(&sm->s_minkey, key);
                            }
                        }
                    }
                }
            }
            __syncthreads();
            const int nk = k + 2;
            if (nk < NTILES && tid == 0) {
                const unsigned mb = b ? mb1 : mb0;
                const unsigned bu = b ? bu1 : bu0;
                mbar_expect(mb, TILE_BYTES);
                bulk_g2s(bu, rowb + (size_t)nk * TILE_BYTES, TILE_BYTES, mb);
            }
        }

        // ---- acquire next row, prefetch its first tiles (overlaps selection) ----
        if (tid == 0) sm->s_next = GRID + atomicAdd(&g_ctr, 1);
        __syncthreads();
        const int nextrow = sm->s_next;
        int nc = sm->nCand;
        const bool ok = (nc >= KSEL && nc <= MAXB);
        if (ok && nextrow < nrows && tid == 0) {
            const char* nb = (const char*)(logits + (size_t)nextrow * VT);
            mbar_expect(mb0, TILE_BYTES);
            bulk_g2s(bu0, nb, TILE_BYTES, mb0);
            mbar_expect(mb1, TILE_BYTES);
            bulk_g2s(bu1, nb + TILE_BYTES, TILE_BYTES, mb1);
        }

        // ---- rare fallback: LDG rescan with sampled-stats threshold ----
        if (!ok) {
            const float4* rp = (const float4*)rowf;
            float thrVal;
            {
                float x = rowf[tid * (VT / THREADS)];
                sm->fred[tid] = x;
                sm->fred2[tid] = x * x;
                __syncthreads();
                for (int s = THREADS / 2; s > 0; s >>= 1) {
                    if (tid < s) {
                        sm->fred[tid] += sm->fred[tid + s];
                        sm->fred2[tid] += sm->fred2[tid + s];
                    }
                    __syncthreads();
                }
                if (tid == 0) {
                    float mean = sm->fred[0] * (1.0f / THREADS);
                    float var  = sm->fred2[0] * (1.0f / THREADS) - mean * mean;
                    sm->s_mean = mean;
                    sm->s_std  = sqrtf(fmaxf(var, 1e-12f));
                }
                __syncthreads();
                thrVal = sm->s_mean + 2.45f * sm->s_std;
                if (fabsf(thrVal - thr0) < 0.05f * sm->s_std)
                    thrVal += (nc < KSEL) ? -0.60f * sm->s_std : 0.35f * sm->s_std;
            }
            for (int attempt = 0; attempt < 10; attempt++) {
                if (tid == 0) { sm->nCand = 0; sm->s_maxkey = 0u; sm->s_minkey = 0xFFFFFFFFu; }
                __syncthreads();
                for (int i = tid; i < VT / 4; i += THREADS) {
                    float4 v = rp[i];
                    float m = fmaxf(fmaxf(v.x, v.y), fmaxf(v.z, v.w));
                    if (m >= thrVal) {
                        float a4[4] = {v.x, v.y, v.z, v.w};
#pragma unroll
                        for (int j = 0; j < 4; j++) {
                            if (a4[j] >= thrVal) {
                                unsigned key = f2k(a4[j]);
                                int p = atomicAdd(&sm->nCand, 1);
                                if (p < MAXB) {
                                    sm->tKey0[p] = key;
                                    sm->tIdx0[p] = (unsigned)(i * 4 + j);
                                    atomicMax(&sm->s_maxkey, key);
                                    atomicMin(&sm->s_minkey, key);
                                }
                            }
                        }
                    }
                }
                __syncthreads();
                nc = sm->nCand;
                if (nc >= KSEL && nc <= MAXB) break;
                if (nc < KSEL) thrVal -= 0.60f * sm->s_std + 1e-6f;
                else           thrVal += 0.35f * sm->s_std + 1e-6f;
                __syncthreads();
            }
            if (nextrow < nrows && tid == 0) {   // now safe to prefetch next row
                const char* nb = (const char*)(logits + (size_t)nextrow * VT);
                mbar_expect(mb0, TILE_BYTES);
                bulk_g2s(bu0, nb, TILE_BYTES, mb0);
                mbar_expect(mb1, TILE_BYTES);
                bulk_g2s(bu1, nb + TILE_BYTES, TILE_BYTES, mb1);
            }
        }

        // ---- zero own output row ----
        {
            float4 z = make_float4(0.f, 0.f, 0.f, 0.f);
            float4* op = (float4*)orow;
            for (int i = tid; i < VS / 4; i += THREADS) op[i] = z;
        }

        // ---- exact top-KSEL: in-place byte-radix (register-staged partition) ----
        unsigned* hist = (unsigned*)sm->fred;      // 256 x 4B histogram
        int curN = nc < MAXB ? nc : MAXB;
        int need = KSEL;
        const unsigned keyxor = sm->s_minkey ^ sm->s_maxkey;
        int level = (keyxor == 0u) ? -1 : (3 - (__clz(keyxor) >> 3));
        __syncthreads();

        for (; level >= 0 && need > 0; level--) {
            if (curN == need) break;               // take all remaining
            if (tid < 256) hist[tid] = 0u;
            __syncthreads();
            const int sh = level * 8;
            // stage my entries in registers + histogram
            unsigned myK[4], myI[4];
            int mycnt = 0;
            for (int p = tid; p < curN; p += THREADS) {
                unsigned key = sm->tKey0[p];
                myK[mycnt] = key;
                myI[mycnt] = sm->tIdx0[p];
                mycnt++;
                atomicAdd(&hist[(key >> sh) & 0xFFu], 1u);
            }
            __syncthreads();
            if (tid < 32) {
                unsigned local[8];
                unsigned part = 0;
#pragma unroll
                for (int j = 0; j < 8; j++) {
                    local[j] = hist[255 - (tid * 8 + j)];
                    part += local[j];
                }
                unsigned incl = part;
#pragma unroll
                for (int off = 1; off < 32; off <<= 1) {
                    unsigned v = __shfl_up_sync(0xffffffffu, incl, off);
                    if (tid >= off) incl += v;
                }
                unsigned before = incl - part;
                if (before < (unsigned)need && incl >= (unsigned)need) {
                    unsigned cum = before;
#pragma unroll
                    for (int j = 0; j < 8; j++) {
                        unsigned cj = local[j];
                        if (cum + cj >= (unsigned)need) {
                            sm->s_bin = 255 - (tid * 8 + j);
                            sm->s_above = cum;
                            break;
                        }
                        cum += cj;
                    }
                }
            }
            if (tid == 0) sm->nNext = 0;
            __syncthreads();
            const int c = sm->s_bin;
            const int G = (int)sm->s_above;
            for (int j = 0; j < mycnt; j++) {
                int byte = (int)((myK[j] >> sh) & 0xFFu);
                if (byte > c) {
                    int q = atomicAdd(&sm->selCount, 1);
                    sm->selKey[q] = myK[j]; sm->selIdx[q] = myI[j];
                } else if (byte == c) {
                    int q = atomicAdd(&sm->nNext, 1);
                    sm->tKey0[q] = myK[j]; sm->tIdx0[q] = myI[j];
                }
            }
            __syncthreads();
            need -= G;
            curN = sm->nNext;
            __syncthreads();
        }

        if (need > 0) {
            if (curN == need) {
                for (int p = tid; p < curN; p += THREADS) {
                    int q = atomicAdd(&sm->selCount, 1);
                    sm->selKey[q] = sm->tKey0[p]; sm->selIdx[q] = sm->tIdx0[p];
                }
            } else {
                // identical keys remain; take `need` smallest indices
                for (int p = tid; p < curN; p += THREADS) {
                    unsigned my = sm->tIdx0[p];
                    int rank = 0;
                    for (int j = 0; j < curN; j++) rank += (sm->tIdx0[j] < my);
                    if (rank < need) {
                        int q = atomicAdd(&sm->selCount, 1);
                        sm->selKey[q] = sm->tKey0[p]; sm->selIdx[q] = my;
                    }
                }
            }
            __syncthreads();
        }

        const float vmax = k2f(sm->s_maxkey);

        // ---- weights + denominator ----
        float w = 0.0f;
        if (tid < KSEL) {
            w = exp2f((k2f(sm->selKey[tid]) - vmax) * 0.36067376022224085f);
            float ws = w;
#pragma unroll
            for (int off = 16; off > 0; off >>= 1)
                ws += __shfl_xor_sync(0xffffffffu, ws, off);
            if ((tid & 31) == 0) atomicAdd(&sm->s_denom, ws);
        }
        __syncthreads();
        const float inv = 1.0f / sm->s_denom;

        // ---- scatter ----
        if (tid < KSEL) {
            unsigned idx = sm->selIdx[tid];
            int sid;
            if (sm->s_is64) sid = (int)((const long long*)mapping)[idx];
            else            sid = ((const int*)mapping)[idx];
            atomicAdd(&orow[sid], w * inv);
        }
        __syncthreads();
        row = nextrow;
    }

    // ---- self-reset for graph replay ----
    __syncthreads();
    if (tid == 0) {
        __threadfence();
        int d = atomicAdd(&g_done, 1);
        if (d == (int)gridDim.x - 1) {
            g_ctr = 0;
            g_done = 0;
            __threadfence();
        }
    }
}

extern "C" void kernel_launch(void* const* d_in, const int* in_sizes, int n_in,
                              void* d_out, int out_size) {
    const float* logits  = (const float*)d_in[0];
    const void*  mapping = d_in[1];
    float* out = (float*)d_out;
    int rows = in_sizes[0] / VT;   // B*T = 2048
    int shbytes = (int)sizeof(Smem);
    cudaFuncSetAttribute(vocab_project_kernel,
                         cudaFuncAttributeMaxDynamicSharedMemorySize, shbytes);
    vocab_project_kernel<<<GRID, THREADS, shbytes>>>(logits, mapping, out, rows);
}

// round 15
// speedup vs baseline: 1.2504x; 1.0091x over previous
#include <cuda_runtime.h>
#include <cuda_bf16.h>
#include <cstdint>

#define THREADS 512
#define VT      128000
#define VS      32000
#define KSEL    256
#define MAXB    2048
#define TILE_F4    1000          // 4000 floats = 16000 bytes per tile
#define TILE_BYTES 16000
#define NTILES     32
#define GRID       592

__device__ int g_ctr = 0;        // rows handed out = GRID + g_ctr
__device__ int g_done = 0;

struct __align__(128) Smem {
    float4   buf[2][TILE_F4];            // 32000 B stream double buffer
    unsigned tKey0[MAXB], tIdx0[MAXB];   // 16384 B candidate store (in-place radix)
    unsigned long long mbar[2];
    unsigned selKey[KSEL], selIdx[KSEL];
    float    fred[THREADS], fred2[THREADS];
    int      s_bin; unsigned s_above;
    int      nCand, selCount, nNext, s_is64, s_next;
    unsigned s_maxkey, s_minkey;
    float    s_mean, s_std, s_denom;
};

__device__ __forceinline__ unsigned f2k(float x) {
    unsigned u = __float_as_uint(x);
    return (u & 0x80000000u) ? ~u : (u | 0x80000000u);
}
__device__ __forceinline__ float k2f(unsigned k) {
    unsigned u = (k & 0x80000000u) ? (k & 0x7fffffffu) : ~k;
    return __uint_as_float(u);
}
__device__ __forceinline__ unsigned s2u(const void* p) {
    unsigned a;
    asm("{ .reg .u64 t; cvta.to.shared.u64 t, %1; cvt.u32.u64 %0, t; }"
        : "=r"(a) : "l"(p));
    return a;
}
__device__ __forceinline__ void mbar_init(unsigned a, unsigned cnt) {
    asm volatile("mbarrier.init.shared.b64 [%0], %1;" :: "r"(a), "r"(cnt) : "memory");
}
__device__ __forceinline__ void mbar_expect(unsigned a, unsigned bytes) {
    asm volatile("mbarrier.arrive.expect_tx.shared.b64 _, [%0], %1;"
                 :: "r"(a), "r"(bytes) : "memory");
}
__device__ __forceinline__ void bulk_g2s(unsigned dst, const void* src,
                                         unsigned bytes, unsigned mbar) {
    asm volatile("cp.async.bulk.shared::cta.global.mbarrier::complete_tx::bytes "
                 "[%0], [%1], %2, [%3];"
                 :: "r"(dst), "l"(src), "r"(bytes), "r"(mbar) : "memory");
}
__device__ __forceinline__ void mbar_wait(unsigned a, unsigned parity) {
    unsigned done;
    asm volatile(
        "{\n\t.reg .pred p;\n\t"
        "mbarrier.try_wait.parity.acquire.cta.shared::cta.b64 p, [%1], %2;\n\t"
        "selp.b32 %0, 1, 0, p;\n\t}"
        : "=r"(done) : "r"(a), "r"(parity) : "memory");
    if (!done) {
        asm volatile(
            "{\n\t.reg .pred P1;\n\t"
            "WL%=:\n\t"
            "mbarrier.try_wait.parity.acquire.cta.shared::cta.b64 P1, [%0], %1, 0x989680;\n\t"
            "@P1 bra.uni WD%=;\n\t"
            "bra.uni WL%=;\n\t"
            "WD%=:\n\t}"
            :: "r"(a), "r"(parity) : "memory");
    }
}

extern __shared__ char smem_raw[];

__global__ void __launch_bounds__(THREADS)
vocab_project_kernel(const float* __restrict__ logits,
                     const void* __restrict__ mapping,
                     float* __restrict__ out,
                     int nrows) {
    Smem* sm = (Smem*)smem_raw;
    const int tid = threadIdx.x;

    const unsigned mb0 = s2u(&sm->mbar[0]);
    const unsigned mb1 = s2u(&sm->mbar[1]);
    const unsigned bu0 = s2u(&sm->buf[0][0]);
    const unsigned bu1 = s2u(&sm->buf[1][0]);

    if (tid == 0) {
        const unsigned* m32 = (const unsigned*)mapping;
        int all0 = 1;
        for (int i = 1; i < 64; i += 2)
            if (m32[i] != 0u) { all0 = 0; break; }
        sm->s_is64 = all0;
        mbar_init(mb0, 1);
        mbar_init(mb1, 1);
    }
    __syncthreads();

    int row = blockIdx.x;                 // first row = blockIdx
    int ph0 = 0, ph1 = 0;                 // persistent mbarrier phases

    // prologue: prefetch tiles 0,1 of first row
    if (row < nrows && tid == 0) {
        const char* rb = (const char*)(logits + (size_t)row * VT);
        mbar_expect(mb0, TILE_BYTES);
        bulk_g2s(bu0, rb, TILE_BYTES, mb0);
        mbar_expect(mb1, TILE_BYTES);
        bulk_g2s(bu1, rb + TILE_BYTES, TILE_BYTES, mb1);
    }

    while (row < nrows) {
        const float* __restrict__ rowf = logits + (size_t)row * VT;
        float* __restrict__ orow = out + (size_t)row * VS;

        if (tid == 0) {
            sm->nCand = 0; sm->selCount = 0; sm->s_denom = 0.0f;
            sm->s_maxkey = 0u; sm->s_minkey = 0xFFFFFFFFu;
        }
        __syncthreads();

        // ---- stream row through double buffer (tiles 0,1 already in flight) ----
        const float thr0 = 2.70f;         // E[count] ~ 445 for N(0,1)
        for (int k = 0; k < NTILES; k++) {
            const int b = k & 1;
            if (b == 0) { mbar_wait(mb0, ph0); ph0 ^= 1; }
            else        { mbar_wait(mb1, ph1); ph1 ^= 1; }
            // acquire next row id while processing tile NTILES-2
            if (k == NTILES - 2 && tid == 0)
                sm->s_next = GRID + atomicAdd(&g_ctr, 1);
            const float4* tb = sm->buf[b];
            const unsigned base = (unsigned)k * (TILE_F4 * 4);
            for (int i = tid; i < TILE_F4; i += THREADS) {
                float4 v = tb[i];
                float m = fmaxf(fmaxf(v.x, v.y), fmaxf(v.z, v.w));
                if (m >= thr0) {
                    float a4[4] = {v.x, v.y, v.z, v.w};
#pragma unroll
                    for (int j = 0; j < 4; j++) {
                        if (a4[j] >= thr0) {
                            unsigned key = f2k(a4[j]);
                            int p = atomicAdd(&sm->nCand, 1);
                            if (p < MAXB) {
                                sm->tKey0[p] = key;
                                sm->tIdx0[p] = base + i * 4 + j;
                                atomicMax(&sm->s_maxkey, key);
                                atomicMin(&sm->s_minkey, key);
                            }
                        }
                    }
                }
            }
            __syncthreads();
            if (tid == 0) {
                const int nk = k + 2;
                if (nk < NTILES) {
                    const unsigned mb = b ? mb1 : mb0;
                    const unsigned bu = b ? bu1 : bu0;
                    mbar_expect(mb, TILE_BYTES);
                    bulk_g2s(bu, (const char*)rowf + (size_t)nk * TILE_BYTES,
                             TILE_BYTES, mb);
                } else {
                    // buffer freed by this sync belongs to next row's tile nk-NTILES
                    const int nt = nk - NTILES;          // 0 or 1
                    const int nextrow = sm->s_next;
                    if (nextrow < nrows) {
                        const char* nb = (const char*)(logits + (size_t)nextrow * VT);
                        const unsigned mb = b ? mb1 : mb0;
                        const unsigned bu = b ? bu1 : bu0;
                        mbar_expect(mb, TILE_BYTES);
                        bulk_g2s(bu, nb + (size_t)nt * TILE_BYTES, TILE_BYTES, mb);
                    }
                }
            }
        }
        __syncthreads();
        const int nextrow = sm->s_next;
        int nc = sm->nCand;
        const bool ok = (nc >= KSEL && nc <= MAXB);

        // ---- rare fallback: LDG rescan with sampled-stats threshold ----
        // (next-row tiles already in flight in the buffers; untouched here)
        if (!ok) {
            const float4* rp = (const float4*)rowf;
            float thrVal;
            {
                float x = rowf[tid * (VT / THREADS)];
                sm->fred[tid] = x;
                sm->fred2[tid] = x * x;
                __syncthreads();
                for (int s = THREADS / 2; s > 0; s >>= 1) {
                    if (tid < s) {
                        sm->fred[tid] += sm->fred[tid + s];
                        sm->fred2[tid] += sm->fred2[tid + s];
                    }
                    __syncthreads();
                }
                if (tid == 0) {
                    float mean = sm->fred[0] * (1.0f / THREADS);
                    float var  = sm->fred2[0] * (1.0f / THREADS) - mean * mean;
                    sm->s_mean = mean;
                    sm->s_std  = sqrtf(fmaxf(var, 1e-12f));
                }
                __syncthreads();
                thrVal = sm->s_mean + 2.45f * sm->s_std;
                if (fabsf(thrVal - thr0) < 0.05f * sm->s_std)
                    thrVal += (nc < KSEL) ? -0.60f * sm->s_std : 0.35f * sm->s_std;
            }
            for (int attempt = 0; attempt < 10; attempt++) {
                if (tid == 0) { sm->nCand = 0; sm->s_maxkey = 0u; sm->s_minkey = 0xFFFFFFFFu; }
                __syncthreads();
                for (int i = tid; i < VT / 4; i += THREADS) {
                    float4 v = rp[i];
                    float m = fmaxf(fmaxf(v.x, v.y), fmaxf(v.z, v.w));
                    if (m >= thrVal) {
                        float a4[4] = {v.x, v.y, v.z, v.w};
#pragma unroll
                        for (int j = 0; j < 4; j++) {
                            if (a4[j] >= thrVal) {
                                unsigned key = f2k(a4[j]);
                                int p = atomicAdd(&sm->nCand, 1);
                                if (p < MAXB) {
                                    sm->tKey0[p] = key;
                                    sm->tIdx0[p] = (unsigned)(i * 4 + j);
                                    atomicMax(&sm->s_maxkey, key);
                                    atomicMin(&sm->s_minkey, key);
                                }
                            }
                        }
                    }
                }
                __syncthreads();
                nc = sm->nCand;
                if (nc >= KSEL && nc <= MAXB) break;
                if (nc < KSEL) thrVal -= 0.60f * sm->s_std + 1e-6f;
                else           thrVal += 0.35f * sm->s_std + 1e-6f;
                __syncthreads();
            }
        }

        // ---- zero own output row ----
        {
            float4 z = make_float4(0.f, 0.f, 0.f, 0.f);
            float4* op = (float4*)orow;
            for (int i = tid; i < VS / 4; i += THREADS) op[i] = z;
        }

        // ---- exact top-KSEL: in-place byte-radix (register-staged partition) ----
        unsigned* hist = (unsigned*)sm->fred;      // 256 x 4B histogram
        int curN = nc < MAXB ? nc : MAXB;
        int need = KSEL;
        const unsigned keyxor = sm->s_minkey ^ sm->s_maxkey;
        int level = (keyxor == 0u) ? -1 : (3 - (__clz(keyxor) >> 3));
        __syncthreads();

        for (; level >= 0 && need > 0; level--) {
            if (curN == need) break;               // take all remaining
            if (tid < 256) hist[tid] = 0u;
            __syncthreads();
            const int sh = level * 8;
            unsigned myK[4], myI[4];
            int mycnt = 0;
            for (int p = tid; p < curN; p += THREADS) {
                unsigned key = sm->tKey0[p];
                myK[mycnt] = key;
                myI[mycnt] = sm->tIdx0[p];
                mycnt++;
                atomicAdd(&hist[(key >> sh) & 0xFFu], 1u);
            }
            __syncthreads();
            if (tid < 32) {
                unsigned local[8];
                unsigned part = 0;
#pragma unroll
                for (int j = 0; j < 8; j++) {
                    local[j] = hist[255 - (tid * 8 + j)];
                    part += local[j];
                }
                unsigned incl = part;
#pragma unroll
                for (int off = 1; off < 32; off <<= 1) {
                    unsigned v = __shfl_up_sync(0xffffffffu, incl, off);
                    if (tid >= off) incl += v;
                }
                unsigned before = incl - part;
                if (before < (unsigned)need && incl >= (unsigned)need) {
                    unsigned cum = before;
#pragma unroll
                    for (int j = 0; j < 8; j++) {
                        unsigned cj = local[j];
                        if (cum + cj >= (unsigned)need) {
                            sm->s_bin = 255 - (tid * 8 + j);
                            sm->s_above = cum;
                            break;
                        }
                        cum += cj;
                    }
                }
            }
            if (tid == 0) sm->nNext = 0;
            __syncthreads();
            const int c = sm->s_bin;
            const int G = (int)sm->s_above;
            for (int j = 0; j < mycnt; j++) {
                int byte = (int)((myK[j] >> sh) & 0xFFu);
                if (byte > c) {
                    int q = atomicAdd(&sm->selCount, 1);
                    sm->selKey[q] = myK[j]; sm->selIdx[q] = myI[j];
                } else if (byte == c) {
                    int q = atomicAdd(&sm->nNext, 1);
                    sm->tKey0[q] = myK[j]; sm->tIdx0[q] = myI[j];
                }
            }
            __syncthreads();
            need -= G;
            curN = sm->nNext;
            __syncthreads();
        }

        if (need > 0) {
            if (curN == need) {
                for (int p = tid; p < curN; p += THREADS) {
                    int q = atomicAdd(&sm->selCount, 1);
                    sm->selKey[q] = sm->tKey0[p]; sm->selIdx[q] = sm->tIdx0[p];
                }
            } else {
                // identical keys remain; take `need` smallest indices
                for (int p = tid; p < curN; p += THREADS) {
                    unsigned my = sm->tIdx0[p];
                    int rank = 0;
                    for (int j = 0; j < curN; j++) rank += (sm->tIdx0[j] < my);
                    if (rank < need) {
                        int q = atomicAdd(&sm->selCount, 1);
                        sm->selKey[q] = sm->tKey0[p]; sm->selIdx[q] = my;
                    }
                }
            }
            __syncthreads();
        }

        const float vmax = k2f(sm->s_maxkey);

        // ---- weights + denominator ----
        float w = 0.0f;
        if (tid < KSEL) {
            w = exp2f((k2f(sm->selKey[tid]) - vmax) * 0.36067376022224085f);
            float ws = w;
#pragma unroll
            for (int off = 16; off > 0; off >>= 1)
                ws += __shfl_xor_sync(0xffffffffu, ws, off);
            if ((tid & 31) == 0) atomicAdd(&sm->s_denom, ws);
        }
        __syncthreads();
        const float inv = 1.0f / sm->s_denom;

        // ---- scatter ----
        if (tid < KSEL) {
            unsigned idx = sm->selIdx[tid];
            int sid;
            if (sm->s_is64) sid = (int)((const long long*)mapping)[idx];
            else            sid = ((const int*)mapping)[idx];
            atomicAdd(&orow[sid], w * inv);
        }
        __syncthreads();
        row = nextrow;
    }

    // ---- self-reset for graph replay ----
    __syncthreads();
    if (tid == 0) {
        __threadfence();
        int d = atomicAdd(&g_done, 1);
        if (d == (int)gridDim.x - 1) {
            g_ctr = 0;
            g_done = 0;
            __threadfence();
        }
    }
}

extern "C" void kernel_launch(void* const* d_in, const int* in_sizes, int n_in,
                              void* d_out, int out_size) {
    const float* logits  = (const float*)d_in[0];
    const void*  mapping = d_in[1];
    float* out = (float*)d_out;
    int rows = in_sizes[0] / VT;   // B*T = 2048
    int shbytes = (int)sizeof(Smem);
    cudaFuncSetAttribute(vocab_project_kernel,
                         cudaFuncAttributeMaxDynamicSharedMemorySize, shbytes);
    vocab_project_kernel<<<GRID, THREADS, shbytes>>>(logits, mapping, out, rows);
}